// round 6
// baseline (speedup 1.0000x reference)
#include <cuda_runtime.h>
#include <stdint.h>

#define U_NODES 100000
#define I_NODES 50000
#define N_NODES 150000
#define H 64
#define UH (U_NODES * H)       // 6,400,000
#define IH (I_NODES * H)       // 3,200,000
#define NH (N_NODES * H)       // 9,600,000
#define E_IN 2000000
#define E_DIR 4000000
#define N_LAYERS 4

#define SCAN_BLK 1024
#define N_SCAN_BLOCKS ((N_NODES + SCAN_BLK - 1) / SCAN_BLK)   // 147

// ---------------- scratch (device globals; no runtime allocation) ------------
__device__ __align__(16) float d_deg[N_NODES];
__device__ __align__(16) float d_dinv[N_NODES];
__device__ __align__(16) int   d_cnt[N_NODES];
__device__ __align__(16) int   d_rowptr[N_NODES + 1];
__device__ __align__(16) int   d_wp[N_NODES];
__device__ __align__(16) int   d_partials[N_SCAN_BLOCKS];
__device__ __align__(16) int2  d_cw[E_DIR];             // packed (col, w bits)
__device__ __align__(16) float d_e0[NH];                // fp32 input embeddings
__device__ __align__(16) float d_Lf[N_LAYERS][NH];      // fp32 layer outputs
__device__ int d_is64;

// ---------------- dtype-robust index read ------------------------------------
// JAX default config downcasts int64 -> int32; edge arrays may be either.
__global__ void detect_kernel(const void* __restrict__ p) {
    if (blockIdx.x == 0 && threadIdx.x == 0) {
        const long long* q = (const long long*)p;
        int is64 = 1;
        for (int i = 0; i < 256; i++) {
            long long v = q[i];
            if (v < 0 || v >= N_NODES) { is64 = 0; break; }
        }
        d_is64 = is64;
    }
}

__device__ __forceinline__ int get_idx(const void* __restrict__ p, int k) {
    if (d_is64) return (int)((const long long*)p)[k];
    return ((const int*)p)[k];
}

// ---------------- build phase -------------------------------------------------

__global__ void zero_kernel() {
    int i = blockIdx.x * blockDim.x + threadIdx.x;
    if (i < N_NODES) { d_deg[i] = 0.0f; d_cnt[i] = 0; }
}

__global__ void deg_kernel(const void* __restrict__ eu,
                           const void* __restrict__ ei,
                           const float* __restrict__ ev) {
    int k = blockIdx.x * blockDim.x + threadIdx.x;
    if (k >= E_IN) return;
    int u  = get_idx(eu, k);
    int it = get_idx(ei, k);
    if ((unsigned)u >= U_NODES || (unsigned)it >= I_NODES) return;  // safety
    it += U_NODES;
    float v = ev[k];
    atomicAdd(&d_deg[u], v);
    atomicAdd(&d_deg[it], v);
    atomicAdd(&d_cnt[u], 1);
    atomicAdd(&d_cnt[it], 1);
}

__global__ void dinv_kernel() {
    int i = blockIdx.x * blockDim.x + threadIdx.x;
    if (i >= N_NODES) return;
    float dg = d_deg[i];
    d_dinv[i] = (dg > 0.0f) ? rsqrtf(fmaxf(dg, 1e-12f)) : 0.0f;
}

__global__ void scan1_kernel() {
    __shared__ int sh[SCAN_BLK];
    int t = threadIdx.x;
    int idx = blockIdx.x * SCAN_BLK + t;
    int v = (idx < N_NODES) ? d_cnt[idx] : 0;
    sh[t] = v;
    __syncthreads();
    for (int off = 1; off < SCAN_BLK; off <<= 1) {
        int x = (t >= off) ? sh[t - off] : 0;
        __syncthreads();
        sh[t] += x;
        __syncthreads();
    }
    if (idx < N_NODES) d_rowptr[idx] = sh[t] - v;   // block-local exclusive
    if (t == SCAN_BLK - 1) d_partials[blockIdx.x] = sh[t];
}

__global__ void scan2_kernel() {
    if (blockIdx.x == 0 && threadIdx.x == 0) {
        int s = 0;
        for (int i = 0; i < N_SCAN_BLOCKS; i++) {
            int v = d_partials[i];
            d_partials[i] = s;
            s += v;
        }
    }
}

__global__ void scan3_kernel() {
    int idx = blockIdx.x * blockDim.x + threadIdx.x;
    if (idx < N_NODES) {
        int rp = d_rowptr[idx] + d_partials[idx >> 10];
        d_rowptr[idx] = rp;
        d_wp[idx] = rp;
    }
    if (idx == 0) d_rowptr[N_NODES] = E_DIR;
}

__global__ void scatter_kernel(const void* __restrict__ eu,
                               const void* __restrict__ ei,
                               const float* __restrict__ ev) {
    int k = blockIdx.x * blockDim.x + threadIdx.x;
    if (k >= E_IN) return;
    int u  = get_idx(eu, k);
    int it = get_idx(ei, k);
    if ((unsigned)u >= U_NODES || (unsigned)it >= I_NODES) return;  // safety
    it += U_NODES;
    float v = ev[k];
    float w = d_dinv[u] * v * d_dinv[it];   // symmetric weight
    int wb = __float_as_int(w);
    int p0 = atomicAdd(&d_wp[u], 1);
    d_cw[p0] = make_int2(it, wb);
    int p1 = atomicAdd(&d_wp[it], 1);
    d_cw[p1] = make_int2(u, wb);
}

// e0 = concat(emb_users, emb_items)
__global__ void init_e_kernel(const float* __restrict__ emb_u,
                              const float* __restrict__ emb_i) {
    int i = blockIdx.x * blockDim.x + threadIdx.x;
    if (i >= NH) return;
    d_e0[i] = (i < UH) ? emb_u[i] : emb_i[i - UH];
}

// ---------------- propagation layers ------------------------------------------
// One warp per destination row (256 B fp32). Lanes 0-15 process even edges,
// lanes 16-31 odd edges; each lane loads one float4 (16 B) of the source row.
// Two edges per warp-instruction stream; shfl_xor(16) combines at the end.

#define GATHER(OFF)                                                           \
    {                                                                         \
        int2 cw = __ldcs(&d_cw[j + (OFF) + hid]);                             \
        float w = __int_as_float(cw.y);                                       \
        float4 v = ((const float4*)(ein + (size_t)cw.x * H))[m];              \
        sum.x += w * v.x; sum.y += w * v.y;                                   \
        sum.z += w * v.z; sum.w += w * v.w;                                   \
    }

__global__ void layer_kernel(int layer) {
    const float* __restrict__ ein  = (layer == 0) ? d_e0 : d_Lf[layer - 1];
    float*       __restrict__ eout = d_Lf[layer];
    int warp = (blockIdx.x * blockDim.x + threadIdx.x) >> 5;
    if (warp >= N_NODES) return;
    int lane = threadIdx.x & 31;
    int hid  = lane >> 4;     // 0: even-parity edges, 1: odd-parity edges
    int m    = lane & 15;     // float4 chunk within the 256 B row
    int s = __ldg(&d_rowptr[warp]);
    int e = __ldg(&d_rowptr[warp + 1]);
    float4 sum = make_float4(0.0f, 0.0f, 0.0f, 0.0f);
    int j = s;
    for (; j + 7 < e; j += 8) { GATHER(0) GATHER(2) GATHER(4) GATHER(6) }
    for (; j + 1 < e; j += 2) { GATHER(0) }
    if (j < e && hid == 0) {   // odd tail edge: even half only
        int2 cw = __ldcs(&d_cw[j]);
        float w = __int_as_float(cw.y);
        float4 v = ((const float4*)(ein + (size_t)cw.x * H))[m];
        sum.x += w * v.x; sum.y += w * v.y;
        sum.z += w * v.z; sum.w += w * v.w;
    }
    sum.x += __shfl_xor_sync(0xffffffffu, sum.x, 16);
    sum.y += __shfl_xor_sync(0xffffffffu, sum.y, 16);
    sum.z += __shfl_xor_sync(0xffffffffu, sum.z, 16);
    sum.w += __shfl_xor_sync(0xffffffffu, sum.w, 16);
    if (hid == 0) {
        ((float4*)(eout + (size_t)warp * H))[m] = sum;
    }
}

// ---------------- epilogue -----------------------------------------------------
// out = [(emb_u + sum_L)/25 | emb_u | (emb_i + sum_L)/25 | emb_i]
__global__ void final_kernel(const float* __restrict__ emb_u,
                             const float* __restrict__ emb_i,
                             float* __restrict__ out, int out_n) {
    const float sc = 1.0f / 25.0f;   // alpha * 1/(L+1) = 1/5 * 1/5
    int i = blockIdx.x * blockDim.x + threadIdx.x;
    if (i >= out_n) return;
    float v;
    if (i < UH) {
        float a = emb_u[i];
        a += d_Lf[0][i] + d_Lf[1][i] + d_Lf[2][i] + d_Lf[3][i];
        v = a * sc;
    } else if (i < 2 * UH) {
        v = emb_u[i - UH];
    } else if (i < 2 * UH + IH) {
        int idx = UH + (i - 2 * UH);
        float a = emb_i[i - 2 * UH];
        a += d_Lf[0][idx] + d_Lf[1][idx] + d_Lf[2][idx] + d_Lf[3][idx];
        v = a * sc;
    } else if (i < 2 * UH + 2 * IH) {
        v = emb_i[i - 2 * UH - IH];
    } else {
        v = 0.0f;
    }
    out[i] = v;
}

// ---------------- launch ------------------------------------------------------

extern "C" void kernel_launch(void* const* d_in, const int* in_sizes, int n_in,
                              void* d_out, int out_size) {
    const float* emb_u = (const float*)d_in[0];
    const float* emb_i = (const float*)d_in[1];
    const void*  eu    = d_in[2];
    const void*  ei    = d_in[3];
    const float* ev    = (const float*)d_in[4];
    float* out = (float*)d_out;

    const int TB = 256;
    int gb_nodes = (N_NODES + TB - 1) / TB;
    int gb_edges = (E_IN + TB - 1) / TB;
    int gb_nh    = (NH + TB - 1) / TB;
    int gb_out   = (out_size + TB - 1) / TB;

    detect_kernel<<<1, 32>>>(eu);
    zero_kernel<<<gb_nodes, TB>>>();
    deg_kernel<<<gb_edges, TB>>>(eu, ei, ev);
    dinv_kernel<<<gb_nodes, TB>>>();
    scan1_kernel<<<N_SCAN_BLOCKS, SCAN_BLK>>>();
    scan2_kernel<<<1, 32>>>();
    scan3_kernel<<<gb_nodes, TB>>>();
    scatter_kernel<<<gb_edges, TB>>>(eu, ei, ev);
    init_e_kernel<<<gb_nh, TB>>>(emb_u, emb_i);

    int layer_blocks = (N_NODES * 32 + TB - 1) / TB;   // warp per row
    layer_kernel<<<layer_blocks, TB>>>(0);
    layer_kernel<<<layer_blocks, TB>>>(1);
    layer_kernel<<<layer_blocks, TB>>>(2);
    layer_kernel<<<layer_blocks, TB>>>(3);

    final_kernel<<<gb_out, TB>>>(emb_u, emb_i, out, out_size);
}

// round 7
// speedup vs baseline: 1.0882x; 1.0882x over previous
#include <cuda_runtime.h>
#include <stdint.h>

#define U_NODES 100000
#define I_NODES 50000
#define N_NODES 150000
#define H 64
#define UH (U_NODES * H)       // 6,400,000
#define IH (I_NODES * H)       // 3,200,000
#define NH (N_NODES * H)       // 9,600,000
#define E_IN 2000000
#define E_DIR 4000000

#define SCAN_BLK 1024
#define N_SCAN_BLOCKS ((N_NODES + SCAN_BLK - 1) / SCAN_BLK)   // 147

// ---------------- scratch (device globals; no runtime allocation) ------------
__device__ __align__(16) float d_deg[N_NODES];
__device__ __align__(16) float d_dinv[N_NODES];
__device__ __align__(16) int   d_cnt[N_NODES];
__device__ __align__(16) int   d_rowptr[N_NODES + 1];
__device__ __align__(16) int   d_wp[N_NODES];
__device__ __align__(16) int   d_partials[N_SCAN_BLOCKS];
__device__ __align__(16) int2  d_cw[E_DIR];     // packed (col, w bits)
__device__ __align__(16) float d_e0[NH];
__device__ __align__(16) float d_e1[NH];
__device__ __align__(16) float d_acc[NH];
__device__ int d_is64;

// ---------------- dtype-robust index read ------------------------------------
// JAX default config downcasts int64 -> int32; edge arrays may be either.
__global__ void detect_kernel(const void* __restrict__ p) {
    if (blockIdx.x == 0 && threadIdx.x == 0) {
        const long long* q = (const long long*)p;
        int is64 = 1;
        for (int i = 0; i < 256; i++) {
            long long v = q[i];
            if (v < 0 || v >= N_NODES) { is64 = 0; break; }
        }
        d_is64 = is64;
    }
}

__device__ __forceinline__ int get_idx(const void* __restrict__ p, int k) {
    if (d_is64) return (int)((const long long*)p)[k];
    return ((const int*)p)[k];
}

// ---------------- build phase -------------------------------------------------

__global__ void zero_kernel() {
    int i = blockIdx.x * blockDim.x + threadIdx.x;
    if (i < N_NODES) { d_deg[i] = 0.0f; d_cnt[i] = 0; }
}

__global__ void deg_kernel(const void* __restrict__ eu,
                           const void* __restrict__ ei,
                           const float* __restrict__ ev) {
    int k = blockIdx.x * blockDim.x + threadIdx.x;
    if (k >= E_IN) return;
    int u  = get_idx(eu, k);
    int it = get_idx(ei, k);
    if ((unsigned)u >= U_NODES || (unsigned)it >= I_NODES) return;  // safety
    it += U_NODES;
    float v = ev[k];
    atomicAdd(&d_deg[u], v);
    atomicAdd(&d_deg[it], v);
    atomicAdd(&d_cnt[u], 1);
    atomicAdd(&d_cnt[it], 1);
}

__global__ void dinv_kernel() {
    int i = blockIdx.x * blockDim.x + threadIdx.x;
    if (i >= N_NODES) return;
    float dg = d_deg[i];
    d_dinv[i] = (dg > 0.0f) ? rsqrtf(fmaxf(dg, 1e-12f)) : 0.0f;
}

__global__ void scan1_kernel() {
    __shared__ int sh[SCAN_BLK];
    int t = threadIdx.x;
    int idx = blockIdx.x * SCAN_BLK + t;
    int v = (idx < N_NODES) ? d_cnt[idx] : 0;
    sh[t] = v;
    __syncthreads();
    for (int off = 1; off < SCAN_BLK; off <<= 1) {
        int x = (t >= off) ? sh[t - off] : 0;
        __syncthreads();
        sh[t] += x;
        __syncthreads();
    }
    if (idx < N_NODES) d_rowptr[idx] = sh[t] - v;   // block-local exclusive
    if (t == SCAN_BLK - 1) d_partials[blockIdx.x] = sh[t];
}

__global__ void scan2_kernel() {
    if (blockIdx.x == 0 && threadIdx.x == 0) {
        int s = 0;
        for (int i = 0; i < N_SCAN_BLOCKS; i++) {
            int v = d_partials[i];
            d_partials[i] = s;
            s += v;
        }
    }
}

__global__ void scan3_kernel() {
    int idx = blockIdx.x * blockDim.x + threadIdx.x;
    if (idx < N_NODES) {
        int rp = d_rowptr[idx] + d_partials[idx >> 10];
        d_rowptr[idx] = rp;
        d_wp[idx] = rp;
    }
    if (idx == 0) d_rowptr[N_NODES] = E_DIR;
}

__global__ void scatter_kernel(const void* __restrict__ eu,
                               const void* __restrict__ ei,
                               const float* __restrict__ ev) {
    int k = blockIdx.x * blockDim.x + threadIdx.x;
    if (k >= E_IN) return;
    int u  = get_idx(eu, k);
    int it = get_idx(ei, k);
    if ((unsigned)u >= U_NODES || (unsigned)it >= I_NODES) return;  // safety
    it += U_NODES;
    float v = ev[k];
    float w = d_dinv[u] * v * d_dinv[it];   // symmetric weight
    int wb = __float_as_int(w);
    int p0 = atomicAdd(&d_wp[u], 1);
    d_cw[p0] = make_int2(it, wb);
    int p1 = atomicAdd(&d_wp[it], 1);
    d_cw[p1] = make_int2(u, wb);
}

// e0 = acc = concat(emb_users, emb_items)
__global__ void init_e_kernel(const float* __restrict__ emb_u,
                              const float* __restrict__ emb_i) {
    int i = blockIdx.x * blockDim.x + threadIdx.x;
    if (i >= NH) return;
    float v = (i < UH) ? emb_u[i] : emb_i[i - UH];
    d_e0[i] = v;
    d_acc[i] = v;
}

// ---------------- propagation layers ------------------------------------------
// One warp per destination row (R4-proven structure): every lane holds dims
// [2*lane, 2*lane+1]; each edge is one broadcast int2 (col,w) load plus one
// whole-warp coalesced float2 row gather. Unrolled x8 for MLP.

#define GATHER(OFF)                                                            \
    {                                                                          \
        int2 cw = d_cw[j + (OFF)];                                             \
        float w = __int_as_float(cw.y);                                        \
        float2 v = *(const float2*)(ein + (size_t)cw.x * H + base);            \
        sum.x += w * v.x;                                                      \
        sum.y += w * v.y;                                                      \
    }

__global__ void layer_kernel(int flip) {
    const float* __restrict__ ein  = flip ? d_e1 : d_e0;
    float*       __restrict__ eout = flip ? d_e0 : d_e1;
    int warp = (blockIdx.x * blockDim.x + threadIdx.x) >> 5;
    int lane = threadIdx.x & 31;
    if (warp >= N_NODES) return;
    int s = d_rowptr[warp];
    int e = d_rowptr[warp + 1];
    float2 sum = make_float2(0.0f, 0.0f);
    int base = lane * 2;
    int j = s;
    for (; j + 7 < e; j += 8) {
        GATHER(0) GATHER(1) GATHER(2) GATHER(3)
        GATHER(4) GATHER(5) GATHER(6) GATHER(7)
    }
    for (; j < e; j++) { GATHER(0) }
    size_t o = (size_t)warp * H + base;
    *(float2*)(eout + o) = sum;
    float2* ap = (float2*)(d_acc + o);
    float2 a = *ap;
    a.x += sum.x;
    a.y += sum.y;
    *ap = a;
}

// ---------------- epilogue -----------------------------------------------------
// out = [acc_users/25 | emb_users | acc_items/25 | emb_items]
__global__ void final_kernel(const float* __restrict__ emb_u,
                             const float* __restrict__ emb_i,
                             float* __restrict__ out, int out_n) {
    const float sc = 1.0f / 25.0f;   // alpha * 1/(L+1) = 1/5 * 1/5
    int i = blockIdx.x * blockDim.x + threadIdx.x;
    if (i >= out_n) return;
    float v;
    if (i < UH)                   v = d_acc[i] * sc;
    else if (i < 2 * UH)          v = emb_u[i - UH];
    else if (i < 2 * UH + IH)     v = d_acc[UH + (i - 2 * UH)] * sc;
    else if (i < 2 * UH + 2 * IH) v = emb_i[i - 2 * UH - IH];
    else                          v = 0.0f;
    out[i] = v;
}

// ---------------- launch ------------------------------------------------------

extern "C" void kernel_launch(void* const* d_in, const int* in_sizes, int n_in,
                              void* d_out, int out_size) {
    const float* emb_u = (const float*)d_in[0];
    const float* emb_i = (const float*)d_in[1];
    const void*  eu    = d_in[2];
    const void*  ei    = d_in[3];
    const float* ev    = (const float*)d_in[4];
    float* out = (float*)d_out;

    const int TB = 256;
    int gb_nodes = (N_NODES + TB - 1) / TB;
    int gb_edges = (E_IN + TB - 1) / TB;
    int gb_nh    = (NH + TB - 1) / TB;
    int gb_out   = (out_size + TB - 1) / TB;

    detect_kernel<<<1, 32>>>(eu);
    zero_kernel<<<gb_nodes, TB>>>();
    deg_kernel<<<gb_edges, TB>>>(eu, ei, ev);
    dinv_kernel<<<gb_nodes, TB>>>();
    scan1_kernel<<<N_SCAN_BLOCKS, SCAN_BLK>>>();
    scan2_kernel<<<1, 32>>>();
    scan3_kernel<<<gb_nodes, TB>>>();
    scatter_kernel<<<gb_edges, TB>>>(eu, ei, ev);
    init_e_kernel<<<gb_nh, TB>>>(emb_u, emb_i);

    int layer_blocks = (N_NODES * 32 + TB - 1) / TB;   // warp per row
    layer_kernel<<<layer_blocks, TB>>>(0);   // e0 -> e1
    layer_kernel<<<layer_blocks, TB>>>(1);   // e1 -> e0
    layer_kernel<<<layer_blocks, TB>>>(0);   // e0 -> e1
    layer_kernel<<<layer_blocks, TB>>>(1);   // e1 -> e0

    final_kernel<<<gb_out, TB>>>(emb_u, emb_i, out, out_size);
}